// round 16
// baseline (speedup 1.0000x reference)
#include <cuda_runtime.h>
#include <cuda_bf16.h>

#define HW 65536
#define IMG 256
#define E76 76
#define E4 304

// ---------------- scratch (device globals; no runtime allocation) ----------------
__device__ float g_hidden[(size_t)2 * E4 * HW];   // conv1x1 output  (159 MB)
__device__ float g_o1[(size_t)2 * E76 * HW];      // irfft2 outputs (pre-LN)
__device__ float g_o2[(size_t)2 * E76 * HW];
__device__ float g_o3[(size_t)2 * E76 * HW];
__device__ float g_vv[(size_t)2 * E76 * HW];      // depthwise v_value

// 8-point twiddle tables (runtime-indexed)
__constant__ float d_TC[8] = {1.f, 0.70710678118654752f, 0.f, -0.70710678118654752f,
                              -1.f, -0.70710678118654752f, 0.f, 0.70710678118654752f};
__constant__ float d_TS[8] = {0.f, 0.70710678118654752f, 1.f, 0.70710678118654752f,
                              0.f, -0.70710678118654752f, -1.f, -0.70710678118654752f};

// compile-time twiddles (fold to immediates in fully-unrolled loops)
__host__ __device__ constexpr float tcos(int a){
    return ((a&7)==0)? 1.f : ((a&7)==1)? 0.70710678118654752f : ((a&7)==2)? 0.f :
           ((a&7)==3)? -0.70710678118654752f : ((a&7)==4)? -1.f :
           ((a&7)==5)? -0.70710678118654752f : ((a&7)==6)? 0.f : 0.70710678118654752f;
}
__host__ __device__ constexpr float tsin(int a){
    return ((a&7)==0)? 0.f : ((a&7)==1)? 0.70710678118654752f : ((a&7)==2)? 1.f :
           ((a&7)==3)? 0.70710678118654752f : ((a&7)==4)? 0.f :
           ((a&7)==5)? -0.70710678118654752f : ((a&7)==6)? -1.f : -0.70710678118654752f;
}

__device__ __forceinline__ float fixv(float v){
    return (fabsf(v) < 1e-10f) ? 1e-10f : v;
}

// =====================================================================
// K1: 1x1 conv  hidden[b][o][p] = sum_c w[o][c] * x[b][c][p]
// grid (5, 256, 2), block 256, dyn smem 81920 B
// =====================================================================
__global__ __launch_bounds__(256) void k1_conv1x1(const float* __restrict__ x,
                                                  const float* __restrict__ w){
    extern __shared__ float sm[];
    float* Xs = sm;            // [64][256]  (c, px)
    float* Ws = sm + 64*256;   // [64][64]   (oc_local, c)
    int oc0 = blockIdx.x * 64;
    int p0  = blockIdx.y * 256;
    int b   = blockIdx.z;
    int tid = threadIdx.x;

    const float* xb = x + ((size_t)b*64)*HW + p0;
    #pragma unroll 8
    for (int c = 0; c < 64; c++)
        Xs[c*256 + tid] = xb[(size_t)c*HW + tid];
    #pragma unroll
    for (int i = 0; i < 16; i++){
        int idx = tid + i*256; int o = idx >> 6, c = idx & 63;
        Ws[idx] = (oc0 + o < E4) ? w[(oc0+o)*64 + c] : 0.f;
    }
    __syncthreads();

    int to = tid >> 5, tp = tid & 31;   // warp = one 'to' group (w broadcast)
    float acc[8][8];
    #pragma unroll
    for (int i = 0; i < 8; i++)
        #pragma unroll
        for (int j = 0; j < 8; j++) acc[i][j] = 0.f;

    for (int c4 = 0; c4 < 64; c4 += 4){
        float4 w4[8];
        #pragma unroll
        for (int i = 0; i < 8; i++)
            w4[i] = *reinterpret_cast<float4*>(&Ws[(to*8 + i)*64 + c4]);
        #pragma unroll
        for (int cc = 0; cc < 4; cc++){
            int c = c4 + cc;
            float4 xa = *reinterpret_cast<float4*>(&Xs[c*256 + tp*8]);
            float4 xc = *reinterpret_cast<float4*>(&Xs[c*256 + tp*8 + 4]);
            float xv[8] = {xa.x, xa.y, xa.z, xa.w, xc.x, xc.y, xc.z, xc.w};
            #pragma unroll
            for (int i = 0; i < 8; i++){
                float wv = (cc==0) ? w4[i].x : (cc==1) ? w4[i].y : (cc==2) ? w4[i].z : w4[i].w;
                #pragma unroll
                for (int j = 0; j < 8; j++) acc[i][j] = fmaf(wv, xv[j], acc[i][j]);
            }
        }
    }

    float* hb = g_hidden + ((size_t)b*E4)*HW + p0 + tp*8;
    #pragma unroll
    for (int i = 0; i < 8; i++){
        int oc = oc0 + to*8 + i;
        if (oc < E4){
            float4 v0 = {acc[i][0], acc[i][1], acc[i][2], acc[i][3]};
            float4 v1 = {acc[i][4], acc[i][5], acc[i][6], acc[i][7]};
            *reinterpret_cast<float4*>(&hb[(size_t)oc*HW])     = v0;
            *reinterpret_cast<float4*>(&hb[(size_t)oc*HW + 4]) = v1;
        }
    }
}

// =====================================================================
// K3: depthwise 3x3 (inline halo) + rfft2 + spectral + 3x irfft2
// 8 threads per (patch, channel); 32 groups/block; 4864 blocks
// =====================================================================
__global__ __launch_bounds__(256) void k3_fft(const float* __restrict__ wdw,
                                              const float* __restrict__ fparam){
    __shared__ float haloS[32][104];   // 10x10 halo per group
    __shared__ float tbS[32][84];      // 8 rows x (5 complex) staging

    int g = threadIdx.x >> 3;
    int r = threadIdx.x & 7;           // row / frequency index
    int G = blockIdx.x*32 + g;
    int e = G % E76;
    int patch = G / E76;               // 0..2047
    int b  = patch >> 10;
    int py = (patch >> 5) & 31;
    int px = patch & 31;
    int y0 = py*8, x0 = px*8;

    float* halo = haloS[g];
    float* tbg  = tbS[g];

    // runtime twiddles for u (or y) = r:  cw[j]=cos(2*pi*r*j/8), sw[j]=sin(...)
    float cw[8], sw[8];
    #pragma unroll
    for (int j = 0; j < 8; j++){
        int a = (r*j) & 7;
        cw[j] = d_TC[a];
        sw[j] = d_TS[a];
    }

    float S[3][10];   // q,k,v spectra, this thread holds row u=r: [2k]=re,[2k+1]=im

    #pragma unroll
    for (int s = 0; s < 4; s++){       // q, k, v, v_value
        int ch = s*E76 + e;
        const float* hs = g_hidden + ((size_t)b*E4 + ch)*HW;
        // cooperative 10x10 halo load with zero-pad at image border
        #pragma unroll
        for (int t = 0; t < 13; t++){
            int m = t*8 + r;
            if (m < 100){
                int hy = m / 10, hx = m - hy*10;
                int gy = y0 + hy - 1, gx = x0 + hx - 1;
                float v = 0.f;
                if (gy >= 0 && gy < IMG && gx >= 0 && gx < IMG) v = hs[gy*IMG + gx];
                halo[m] = v;
            }
        }
        __syncthreads();

        float wd[9];
        #pragma unroll
        for (int t = 0; t < 9; t++) wd[t] = wdw[ch*9 + t];
        float a0[10], a1[10], a2[10];
        #pragma unroll
        for (int t = 0; t < 10; t++){
            a0[t] = halo[r*10 + t];
            a1[t] = halo[r*10 + 10 + t];
            a2[t] = halo[r*10 + 20 + t];
        }
        float d[8];
        #pragma unroll
        for (int c = 0; c < 8; c++){
            d[c] = a0[c]*wd[0] + a0[c+1]*wd[1] + a0[c+2]*wd[2]
                 + a1[c]*wd[3] + a1[c+1]*wd[4] + a1[c+2]*wd[5]
                 + a2[c]*wd[6] + a2[c+1]*wd[7] + a2[c+2]*wd[8];
        }

        if (s < 3){
            // row rfft (8 real -> 5 complex), compile-time twiddles
            #pragma unroll
            for (int k = 0; k < 5; k++){
                float re = 0.f, im = 0.f;
                #pragma unroll
                for (int c = 0; c < 8; c++){
                    re += d[c]*tcos(k*c);
                    im -= d[c]*tsin(k*c);
                }
                tbg[r*10 + 2*k]     = re;
                tbg[r*10 + 2*k + 1] = im;
            }
        } else {
            float* dst = g_vv + ((size_t)b*E76 + e)*HW + (y0 + r)*IMG + x0;
            float4 v0 = {d[0], d[1], d[2], d[3]};
            float4 v1 = {d[4], d[5], d[6], d[7]};
            *reinterpret_cast<float4*>(dst)     = v0;
            *reinterpret_cast<float4*>(dst + 4) = v1;
        }
        __syncthreads();

        if (s < 3){
            // column forward DFT over rows: S[u=r][k] = sum_y t[y][k] e^{-2pi i u y/8}
            #pragma unroll
            for (int k = 0; k < 5; k++){
                float sr = 0.f, si = 0.f;
                #pragma unroll
                for (int u = 0; u < 8; u++){
                    float trr = tbg[u*10 + 2*k];
                    float tii = tbg[u*10 + 2*k + 1];
                    sr += trr*cw[u] + tii*sw[u];
                    si += tii*cw[u] - trr*sw[u];
                }
                S[s][2*k]     = sr;
                S[s][2*k + 1] = si;
            }
        }
        __syncthreads();
    }

    // ---- spectral math + 3x irfft2 (thread holds u=r row of each spectrum) ----
    const float* fp = fparam + e*40 + r*5;   // [76][1][1][8][5]

    #pragma unroll
    for (int m = 0; m < 3; m++){
        float F[10];
        #pragma unroll
        for (int k = 0; k < 5; k++){
            float qr = S[0][2*k], qi = S[0][2*k+1];
            float kr = S[1][2*k], ki = S[1][2*k+1];
            float pm = fp[k];
            float vr = S[2][2*k]*pm, vi = S[2][2*k+1]*pm;
            float vrf = fixv(vr), vif = fixv(vi);
            float pr = fixv(qr*kr - qi*ki);
            float pi = fixv(qr*ki + qi*kr);
            float qka = sqrtf(pr*pr + pi*pi);
            float orr, oii;
            if (m == 1){
                // out2 = |qk| * exp(i*angle(v')) = |qk| * v'/|v'|
                float invv = rsqrtf(vrf*vrf + vif*vif);
                orr = qka * vrf * invv;
                oii = qka * vif * invv;
            } else {
                float qrf = fixv(qr), qif = fixv(qi);
                float krf = fixv(kr), kif = fixv(ki);
                float sr_ = qrf*krf + qif*kif;     // q' * conj(k')  (re)
                float si_ = qif*krf - qrf*kif;     //               (im)
                float prod = (qrf*qrf + qif*qif) * (krf*krf + kif*kif);
                float inv = rsqrtf(fmaxf(prod, 1e-37f));
                float amp = (m == 0) ? sqrtf(vrf*vrf + vif*vif) : qka;
                orr = amp * sr_ * inv;
                oii = amp * si_ * inv;
            }
            F[2*k]   = orr;
            F[2*k+1] = oii;
        }

        // exchange: write my spectrum row u=r
        #pragma unroll
        for (int k = 0; k < 10; k++) tbg[r*10 + k] = F[k];
        __syncthreads();

        // Step A: inverse over u -> t[y=r][k] (includes 1/8)
        float T[10];
        #pragma unroll
        for (int k = 0; k < 5; k++){
            float tr = 0.f, ti = 0.f;
            #pragma unroll
            for (int u = 0; u < 8; u++){
                float fr = tbg[u*10 + 2*k];
                float fi = tbg[u*10 + 2*k + 1];
                tr += fr*cw[u] - fi*sw[u];
                ti += fr*sw[u] + fi*cw[u];
            }
            T[2*k]   = tr * 0.125f;
            T[2*k+1] = ti * 0.125f;
        }

        // Step B: irfft over k (ignores imag of DC and Nyquist, as pocketfft c2r)
        float o[8];
        #pragma unroll
        for (int x = 0; x < 8; x++){
            float acc = T[0] + ((x & 1) ? -T[8] : T[8]);
            #pragma unroll
            for (int k = 1; k <= 3; k++)
                acc += 2.f * (T[2*k]*tcos(k*x) - T[2*k+1]*tsin(k*x));
            o[x] = acc * 0.125f;
        }

        float* base = (m == 0) ? g_o1 : (m == 1) ? g_o2 : g_o3;
        float* dst = base + ((size_t)b*E76 + e)*HW + (y0 + r)*IMG + x0;
        float4 v0 = {o[0], o[1], o[2], o[3]};
        float4 v1 = {o[4], o[5], o[6], o[7]};
        *reinterpret_cast<float4*>(dst)     = v0;
        *reinterpret_cast<float4*>(dst + 4) = v1;
        __syncthreads();
    }
}

// =====================================================================
// K4: layernorm (over E=76, per pixel) + v_value mul + projection GEMM
// grid (1024, 2), block 256, dyn smem 82688 B
// =====================================================================
__global__ __launch_bounds__(256) void k4_proj(const float* __restrict__ wproj,
    const float* __restrict__ ln1w, const float* __restrict__ ln1b,
    const float* __restrict__ ln2w, const float* __restrict__ ln2b,
    const float* __restrict__ ln3w, const float* __restrict__ ln3b,
    float* __restrict__ out){
    extern __shared__ float sm4[];
    float* A  = sm4;              // [228][68]  (cat channels x pixels)
    float* VV = sm4 + 228*68;     // [76][68]
    int pix0 = blockIdx.x * 64;
    int b    = blockIdx.y;
    int tid  = threadIdx.x;

    // stage all 4 arrays, coalesced (64 contiguous pixels per channel row)
    {
        const float* srcs[4] = {g_o1, g_o2, g_o3, g_vv};
        #pragma unroll
        for (int a = 0; a < 4; a++){
            const float* src = srcs[a] + ((size_t)b*E76)*HW + pix0;
            float* dstbuf = (a < 3) ? (A + a*E76*68) : VV;
            #pragma unroll
            for (int it = 0; it < 19; it++){      // 76*64 = 4864 = 19*256
                int idx = it*256 + tid;
                int c = idx >> 6, p = idx & 63;
                dstbuf[c*68 + p] = src[(size_t)c*HW + p];
            }
        }
    }
    __syncthreads();

    // LayerNorm per pixel per array (192 threads: a in 0..2, p in 0..63)
    if (tid < 192){
        int a = tid >> 6, p = tid & 63;
        float* Ab = A + a*E76*68 + p;
        float s0 = 0.f, s1 = 0.f;
        #pragma unroll 4
        for (int c = 0; c < E76; c++){
            float v = Ab[c*68];
            s0 += v;
            s1 += v*v;
        }
        float mu  = s0 * (1.f/76.f);
        float var = s1 * (1.f/76.f) - mu*mu;
        float sc  = rsqrtf(var + 1e-5f);
        const float* lw = (a==0) ? ln1w : (a==1) ? ln2w : ln3w;
        const float* lb = (a==0) ? ln1b : (a==1) ? ln2b : ln3b;
        #pragma unroll 4
        for (int c = 0; c < E76; c++){
            float v = (Ab[c*68] - mu) * sc * lw[c] + lb[c];
            Ab[c*68] = v * VV[c*68 + p];
        }
    }
    __syncthreads();

    // projection GEMM: out[o][p] = sum_{c<228} wproj[o][c] * A[c][p]
    int to = tid >> 4, tp = tid & 15;    // o tile = to*4.., p tile = tp*4..
    float acc[4][4];
    #pragma unroll
    for (int i = 0; i < 4; i++)
        #pragma unroll
        for (int j = 0; j < 4; j++) acc[i][j] = 0.f;

    for (int c = 0; c < 228; c += 4){
        float4 xv[4];
        #pragma unroll
        for (int cc = 0; cc < 4; cc++)
            xv[cc] = *reinterpret_cast<float4*>(&A[(c+cc)*68 + tp*4]);
        #pragma unroll
        for (int i = 0; i < 4; i++){
            float4 w4 = *reinterpret_cast<const float4*>(&wproj[(to*4 + i)*228 + c]);
            acc[i][0] = fmaf(w4.x, xv[0].x, acc[i][0]);
            acc[i][1] = fmaf(w4.x, xv[0].y, acc[i][1]);
            acc[i][2] = fmaf(w4.x, xv[0].z, acc[i][2]);
            acc[i][3] = fmaf(w4.x, xv[0].w, acc[i][3]);
            acc[i][0] = fmaf(w4.y, xv[1].x, acc[i][0]);
            acc[i][1] = fmaf(w4.y, xv[1].y, acc[i][1]);
            acc[i][2] = fmaf(w4.y, xv[1].z, acc[i][2]);
            acc[i][3] = fmaf(w4.y, xv[1].w, acc[i][3]);
            acc[i][0] = fmaf(w4.z, xv[2].x, acc[i][0]);
            acc[i][1] = fmaf(w4.z, xv[2].y, acc[i][1]);
            acc[i][2] = fmaf(w4.z, xv[2].z, acc[i][2]);
            acc[i][3] = fmaf(w4.z, xv[2].w, acc[i][3]);
            acc[i][0] = fmaf(w4.w, xv[3].x, acc[i][0]);
            acc[i][1] = fmaf(w4.w, xv[3].y, acc[i][1]);
            acc[i][2] = fmaf(w4.w, xv[3].z, acc[i][2]);
            acc[i][3] = fmaf(w4.w, xv[3].w, acc[i][3]);
        }
    }

    #pragma unroll
    for (int i = 0; i < 4; i++){
        int o = to*4 + i;
        float4 v = {acc[i][0], acc[i][1], acc[i][2], acc[i][3]};
        *reinterpret_cast<float4*>(&out[((size_t)(b*64 + o))*HW + pix0 + tp*4]) = v;
    }
}

// =====================================================================
extern "C" void kernel_launch(void* const* d_in, const int* in_sizes, int n_in,
                              void* d_out, int out_size) {
    const float* x       = (const float*)d_in[0];
    const float* w_hidden= (const float*)d_in[1];
    const float* w_dw    = (const float*)d_in[2];
    const float* w_proj  = (const float*)d_in[3];
    const float* fparam  = (const float*)d_in[4];
    const float* ln1w    = (const float*)d_in[5];
    const float* ln1b    = (const float*)d_in[6];
    const float* ln2w    = (const float*)d_in[7];
    const float* ln2b    = (const float*)d_in[8];
    const float* ln3w    = (const float*)d_in[9];
    const float* ln3b    = (const float*)d_in[10];
    float* out = (float*)d_out;

    static bool attr_done = false;
    if (!attr_done){
        cudaFuncSetAttribute(k1_conv1x1, cudaFuncAttributeMaxDynamicSharedMemorySize, 81920);
        cudaFuncSetAttribute(k4_proj,    cudaFuncAttributeMaxDynamicSharedMemorySize, 82688);
        attr_done = true;
    }

    k1_conv1x1<<<dim3(5, 256, 2), 256, 81920>>>(x, w_hidden);
    k3_fft<<<4864, 256>>>(w_dw, fparam);
    k4_proj<<<dim3(1024, 2), 256, 82688>>>(w_proj, ln1w, ln1b, ln2w, ln2b, ln3w, ln3b, out);
}

// round 17
// speedup vs baseline: 1.0005x; 1.0005x over previous
#include <cuda_runtime.h>
#include <cuda_bf16.h>

#define HW 65536
#define IMG 256
#define E76 76
#define E4 304

// ---------------- scratch (device globals; no runtime allocation) ----------------
__device__ float g_hidden[(size_t)2 * E4 * HW];   // conv1x1 output  (159 MB)
__device__ float g_o1[(size_t)2 * E76 * HW];      // irfft2 outputs (pre-LN)
__device__ float g_o2[(size_t)2 * E76 * HW];
__device__ float g_o3[(size_t)2 * E76 * HW];
__device__ float g_vv[(size_t)2 * E76 * HW];      // depthwise v_value

// 8-point twiddle tables (runtime-indexed)
__constant__ float d_TC[8] = {1.f, 0.70710678118654752f, 0.f, -0.70710678118654752f,
                              -1.f, -0.70710678118654752f, 0.f, 0.70710678118654752f};
__constant__ float d_TS[8] = {0.f, 0.70710678118654752f, 1.f, 0.70710678118654752f,
                              0.f, -0.70710678118654752f, -1.f, -0.70710678118654752f};

// compile-time twiddles (fold to immediates in fully-unrolled loops)
__host__ __device__ constexpr float tcos(int a){
    return ((a&7)==0)? 1.f : ((a&7)==1)? 0.70710678118654752f : ((a&7)==2)? 0.f :
           ((a&7)==3)? -0.70710678118654752f : ((a&7)==4)? -1.f :
           ((a&7)==5)? -0.70710678118654752f : ((a&7)==6)? 0.f : 0.70710678118654752f;
}
__host__ __device__ constexpr float tsin(int a){
    return ((a&7)==0)? 0.f : ((a&7)==1)? 0.70710678118654752f : ((a&7)==2)? 1.f :
           ((a&7)==3)? 0.70710678118654752f : ((a&7)==4)? 0.f :
           ((a&7)==5)? -0.70710678118654752f : ((a&7)==6)? -1.f : -0.70710678118654752f;
}

__device__ __forceinline__ float fixv(float v){
    return (fabsf(v) < 1e-10f) ? 1e-10f : v;
}

// =====================================================================
// K1: 1x1 conv  hidden[b][o][p] = sum_c w[o][c] * x[b][c][p]
// grid (5, 256, 2), block 256, dyn smem 81920 B
// =====================================================================
__global__ __launch_bounds__(256) void k1_conv1x1(const float* __restrict__ x,
                                                  const float* __restrict__ w){
    extern __shared__ float sm[];
    float* Xs = sm;            // [64][256]  (c, px)
    float* Ws = sm + 64*256;   // [64][64]   (oc_local, c)
    int oc0 = blockIdx.x * 64;
    int p0  = blockIdx.y * 256;
    int b   = blockIdx.z;
    int tid = threadIdx.x;

    const float* xb = x + ((size_t)b*64)*HW + p0;
    #pragma unroll 8
    for (int c = 0; c < 64; c++)
        Xs[c*256 + tid] = xb[(size_t)c*HW + tid];
    #pragma unroll
    for (int i = 0; i < 16; i++){
        int idx = tid + i*256; int o = idx >> 6, c = idx & 63;
        Ws[idx] = (oc0 + o < E4) ? w[(oc0+o)*64 + c] : 0.f;
    }
    __syncthreads();

    int to = tid >> 5, tp = tid & 31;   // warp = one 'to' group (w broadcast)
    float acc[8][8];
    #pragma unroll
    for (int i = 0; i < 8; i++)
        #pragma unroll
        for (int j = 0; j < 8; j++) acc[i][j] = 0.f;

    for (int c4 = 0; c4 < 64; c4 += 4){
        float4 w4[8];
        #pragma unroll
        for (int i = 0; i < 8; i++)
            w4[i] = *reinterpret_cast<float4*>(&Ws[(to*8 + i)*64 + c4]);
        #pragma unroll
        for (int cc = 0; cc < 4; cc++){
            int c = c4 + cc;
            float4 xa = *reinterpret_cast<float4*>(&Xs[c*256 + tp*8]);
            float4 xc = *reinterpret_cast<float4*>(&Xs[c*256 + tp*8 + 4]);
            float xv[8] = {xa.x, xa.y, xa.z, xa.w, xc.x, xc.y, xc.z, xc.w};
            #pragma unroll
            for (int i = 0; i < 8; i++){
                float wv = (cc==0) ? w4[i].x : (cc==1) ? w4[i].y : (cc==2) ? w4[i].z : w4[i].w;
                #pragma unroll
                for (int j = 0; j < 8; j++) acc[i][j] = fmaf(wv, xv[j], acc[i][j]);
            }
        }
    }

    float* hb = g_hidden + ((size_t)b*E4)*HW + p0 + tp*8;
    #pragma unroll
    for (int i = 0; i < 8; i++){
        int oc = oc0 + to*8 + i;
        if (oc < E4){
            float4 v0 = {acc[i][0], acc[i][1], acc[i][2], acc[i][3]};
            float4 v1 = {acc[i][4], acc[i][5], acc[i][6], acc[i][7]};
            *reinterpret_cast<float4*>(&hb[(size_t)oc*HW])     = v0;
            *reinterpret_cast<float4*>(&hb[(size_t)oc*HW + 4]) = v1;
        }
    }
}

// =====================================================================
// K3: depthwise 3x3 (inline halo) + rfft2 + spectral + 3x irfft2
// 8 threads per (patch, channel); 32 groups/block; 4864 blocks
// =====================================================================
__global__ __launch_bounds__(256) void k3_fft(const float* __restrict__ wdw,
                                              const float* __restrict__ fparam){
    __shared__ float haloS[32][104];   // 10x10 halo per group
    __shared__ float tbS[32][84];      // 8 rows x (5 complex) staging

    int g = threadIdx.x >> 3;
    int r = threadIdx.x & 7;           // row / frequency index
    int G = blockIdx.x*32 + g;
    int e = G % E76;
    int patch = G / E76;               // 0..2047
    int b  = patch >> 10;
    int py = (patch >> 5) & 31;
    int px = patch & 31;
    int y0 = py*8, x0 = px*8;

    float* halo = haloS[g];
    float* tbg  = tbS[g];

    // runtime twiddles for u (or y) = r:  cw[j]=cos(2*pi*r*j/8), sw[j]=sin(...)
    float cw[8], sw[8];
    #pragma unroll
    for (int j = 0; j < 8; j++){
        int a = (r*j) & 7;
        cw[j] = d_TC[a];
        sw[j] = d_TS[a];
    }

    float S[3][10];   // q,k,v spectra, this thread holds row u=r: [2k]=re,[2k+1]=im

    #pragma unroll
    for (int s = 0; s < 4; s++){       // q, k, v, v_value
        int ch = s*E76 + e;
        const float* hs = g_hidden + ((size_t)b*E4 + ch)*HW;
        // cooperative 10x10 halo load with zero-pad at image border
        #pragma unroll
        for (int t = 0; t < 13; t++){
            int m = t*8 + r;
            if (m < 100){
                int hy = m / 10, hx = m - hy*10;
                int gy = y0 + hy - 1, gx = x0 + hx - 1;
                float v = 0.f;
                if (gy >= 0 && gy < IMG && gx >= 0 && gx < IMG) v = hs[gy*IMG + gx];
                halo[m] = v;
            }
        }
        __syncthreads();

        float wd[9];
        #pragma unroll
        for (int t = 0; t < 9; t++) wd[t] = wdw[ch*9 + t];
        float a0[10], a1[10], a2[10];
        #pragma unroll
        for (int t = 0; t < 10; t++){
            a0[t] = halo[r*10 + t];
            a1[t] = halo[r*10 + 10 + t];
            a2[t] = halo[r*10 + 20 + t];
        }
        float d[8];
        #pragma unroll
        for (int c = 0; c < 8; c++){
            d[c] = a0[c]*wd[0] + a0[c+1]*wd[1] + a0[c+2]*wd[2]
                 + a1[c]*wd[3] + a1[c+1]*wd[4] + a1[c+2]*wd[5]
                 + a2[c]*wd[6] + a2[c+1]*wd[7] + a2[c+2]*wd[8];
        }

        if (s < 3){
            // row rfft (8 real -> 5 complex), compile-time twiddles
            #pragma unroll
            for (int k = 0; k < 5; k++){
                float re = 0.f, im = 0.f;
                #pragma unroll
                for (int c = 0; c < 8; c++){
                    re += d[c]*tcos(k*c);
                    im -= d[c]*tsin(k*c);
                }
                tbg[r*10 + 2*k]     = re;
                tbg[r*10 + 2*k + 1] = im;
            }
        } else {
            float* dst = g_vv + ((size_t)b*E76 + e)*HW + (y0 + r)*IMG + x0;
            float4 v0 = {d[0], d[1], d[2], d[3]};
            float4 v1 = {d[4], d[5], d[6], d[7]};
            *reinterpret_cast<float4*>(dst)     = v0;
            *reinterpret_cast<float4*>(dst + 4) = v1;
        }
        __syncthreads();

        if (s < 3){
            // column forward DFT over rows: S[u=r][k] = sum_y t[y][k] e^{-2pi i u y/8}
            #pragma unroll
            for (int k = 0; k < 5; k++){
                float sr = 0.f, si = 0.f;
                #pragma unroll
                for (int u = 0; u < 8; u++){
                    float trr = tbg[u*10 + 2*k];
                    float tii = tbg[u*10 + 2*k + 1];
                    sr += trr*cw[u] + tii*sw[u];
                    si += tii*cw[u] - trr*sw[u];
                }
                S[s][2*k]     = sr;
                S[s][2*k + 1] = si;
            }
        }
        __syncthreads();
    }

    // ---- spectral math + 3x irfft2 (thread holds u=r row of each spectrum) ----
    const float* fp = fparam + e*40 + r*5;   // [76][1][1][8][5]

    #pragma unroll
    for (int m = 0; m < 3; m++){
        float F[10];
        #pragma unroll
        for (int k = 0; k < 5; k++){
            float qr = S[0][2*k], qi = S[0][2*k+1];
            float kr = S[1][2*k], ki = S[1][2*k+1];
            float pm = fp[k];
            float vr = S[2][2*k]*pm, vi = S[2][2*k+1]*pm;
            float vrf = fixv(vr), vif = fixv(vi);
            float pr = fixv(qr*kr - qi*ki);
            float pi = fixv(qr*ki + qi*kr);
            float qka = sqrtf(pr*pr + pi*pi);
            float orr, oii;
            if (m == 1){
                // out2 = |qk| * exp(i*angle(v')) = |qk| * v'/|v'|
                float invv = rsqrtf(vrf*vrf + vif*vif);
                orr = qka * vrf * invv;
                oii = qka * vif * invv;
            } else {
                float qrf = fixv(qr), qif = fixv(qi);
                float krf = fixv(kr), kif = fixv(ki);
                float sr_ = qrf*krf + qif*kif;     // q' * conj(k')  (re)
                float si_ = qif*krf - qrf*kif;     //               (im)
                float prod = (qrf*qrf + qif*qif) * (krf*krf + kif*kif);
                float inv = rsqrtf(fmaxf(prod, 1e-37f));
                float amp = (m == 0) ? sqrtf(vrf*vrf + vif*vif) : qka;
                orr = amp * sr_ * inv;
                oii = amp * si_ * inv;
            }
            F[2*k]   = orr;
            F[2*k+1] = oii;
        }

        // exchange: write my spectrum row u=r
        #pragma unroll
        for (int k = 0; k < 10; k++) tbg[r*10 + k] = F[k];
        __syncthreads();

        // Step A: inverse over u -> t[y=r][k] (includes 1/8)
        float T[10];
        #pragma unroll
        for (int k = 0; k < 5; k++){
            float tr = 0.f, ti = 0.f;
            #pragma unroll
            for (int u = 0; u < 8; u++){
                float fr = tbg[u*10 + 2*k];
                float fi = tbg[u*10 + 2*k + 1];
                tr += fr*cw[u] - fi*sw[u];
                ti += fr*sw[u] + fi*cw[u];
            }
            T[2*k]   = tr * 0.125f;
            T[2*k+1] = ti * 0.125f;
        }

        // Step B: irfft over k (ignores imag of DC and Nyquist, as pocketfft c2r)
        float o[8];
        #pragma unroll
        for (int x = 0; x < 8; x++){
            float acc = T[0] + ((x & 1) ? -T[8] : T[8]);
            #pragma unroll
            for (int k = 1; k <= 3; k++)
                acc += 2.f * (T[2*k]*tcos(k*x) - T[2*k+1]*tsin(k*x));
            o[x] = acc * 0.125f;
        }

        float* base = (m == 0) ? g_o1 : (m == 1) ? g_o2 : g_o3;
        float* dst = base + ((size_t)b*E76 + e)*HW + (y0 + r)*IMG + x0;
        float4 v0 = {o[0], o[1], o[2], o[3]};
        float4 v1 = {o[4], o[5], o[6], o[7]};
        *reinterpret_cast<float4*>(dst)     = v0;
        *reinterpret_cast<float4*>(dst + 4) = v1;
        __syncthreads();
    }
}

// =====================================================================
// K4: layernorm (over E=76, per pixel) + v_value mul + projection GEMM
// grid (1024, 2), block 256, dyn smem 82688 B
// =====================================================================
__global__ __launch_bounds__(256) void k4_proj(const float* __restrict__ wproj,
    const float* __restrict__ ln1w, const float* __restrict__ ln1b,
    const float* __restrict__ ln2w, const float* __restrict__ ln2b,
    const float* __restrict__ ln3w, const float* __restrict__ ln3b,
    float* __restrict__ out){
    extern __shared__ float sm4[];
    float* A  = sm4;              // [228][68]  (cat channels x pixels)
    float* VV = sm4 + 228*68;     // [76][68]
    int pix0 = blockIdx.x * 64;
    int b    = blockIdx.y;
    int tid  = threadIdx.x;

    // stage all 4 arrays, coalesced (64 contiguous pixels per channel row)
    {
        const float* srcs[4] = {g_o1, g_o2, g_o3, g_vv};
        #pragma unroll
        for (int a = 0; a < 4; a++){
            const float* src = srcs[a] + ((size_t)b*E76)*HW + pix0;
            float* dstbuf = (a < 3) ? (A + a*E76*68) : VV;
            #pragma unroll
            for (int it = 0; it < 19; it++){      // 76*64 = 4864 = 19*256
                int idx = it*256 + tid;
                int c = idx >> 6, p = idx & 63;
                dstbuf[c*68 + p] = src[(size_t)c*HW + p];
            }
        }
    }
    __syncthreads();

    // LayerNorm per pixel per array (192 threads: a in 0..2, p in 0..63)
    if (tid < 192){
        int a = tid >> 6, p = tid & 63;
        float* Ab = A + a*E76*68 + p;
        float s0 = 0.f, s1 = 0.f;
        #pragma unroll 4
        for (int c = 0; c < E76; c++){
            float v = Ab[c*68];
            s0 += v;
            s1 += v*v;
        }
        float mu  = s0 * (1.f/76.f);
        float var = s1 * (1.f/76.f) - mu*mu;
        float sc  = rsqrtf(var + 1e-5f);
        const float* lw = (a==0) ? ln1w : (a==1) ? ln2w : ln3w;
        const float* lb = (a==0) ? ln1b : (a==1) ? ln2b : ln3b;
        #pragma unroll 4
        for (int c = 0; c < E76; c++){
            float v = (Ab[c*68] - mu) * sc * lw[c] + lb[c];
            Ab[c*68] = v * VV[c*68 + p];
        }
    }
    __syncthreads();

    // projection GEMM: out[o][p] = sum_{c<228} wproj[o][c] * A[c][p]
    int to = tid >> 4, tp = tid & 15;    // o tile = to*4.., p tile = tp*4..
    float acc[4][4];
    #pragma unroll
    for (int i = 0; i < 4; i++)
        #pragma unroll
        for (int j = 0; j < 4; j++) acc[i][j] = 0.f;

    for (int c = 0; c < 228; c += 4){
        float4 xv[4];
        #pragma unroll
        for (int cc = 0; cc < 4; cc++)
            xv[cc] = *reinterpret_cast<float4*>(&A[(c+cc)*68 + tp*4]);
        #pragma unroll
        for (int i = 0; i < 4; i++){
            float4 w4 = *reinterpret_cast<const float4*>(&wproj[(to*4 + i)*228 + c]);
            acc[i][0] = fmaf(w4.x, xv[0].x, acc[i][0]);
            acc[i][1] = fmaf(w4.x, xv[0].y, acc[i][1]);
            acc[i][2] = fmaf(w4.x, xv[0].z, acc[i][2]);
            acc[i][3] = fmaf(w4.x, xv[0].w, acc[i][3]);
            acc[i][0] = fmaf(w4.y, xv[1].x, acc[i][0]);
            acc[i][1] = fmaf(w4.y, xv[1].y, acc[i][1]);
            acc[i][2] = fmaf(w4.y, xv[1].z, acc[i][2]);
            acc[i][3] = fmaf(w4.y, xv[1].w, acc[i][3]);
            acc[i][0] = fmaf(w4.z, xv[2].x, acc[i][0]);
            acc[i][1] = fmaf(w4.z, xv[2].y, acc[i][1]);
            acc[i][2] = fmaf(w4.z, xv[2].z, acc[i][2]);
            acc[i][3] = fmaf(w4.z, xv[2].w, acc[i][3]);
            acc[i][0] = fmaf(w4.w, xv[3].x, acc[i][0]);
            acc[i][1] = fmaf(w4.w, xv[3].y, acc[i][1]);
            acc[i][2] = fmaf(w4.w, xv[3].z, acc[i][2]);
            acc[i][3] = fmaf(w4.w, xv[3].w, acc[i][3]);
        }
    }

    #pragma unroll
    for (int i = 0; i < 4; i++){
        int o = to*4 + i;
        float4 v = {acc[i][0], acc[i][1], acc[i][2], acc[i][3]};
        *reinterpret_cast<float4*>(&out[((size_t)(b*64 + o))*HW + pix0 + tp*4]) = v;
    }
}

// =====================================================================
extern "C" void kernel_launch(void* const* d_in, const int* in_sizes, int n_in,
                              void* d_out, int out_size) {
    const float* x       = (const float*)d_in[0];
    const float* w_hidden= (const float*)d_in[1];
    const float* w_dw    = (const float*)d_in[2];
    const float* w_proj  = (const float*)d_in[3];
    const float* fparam  = (const float*)d_in[4];
    const float* ln1w    = (const float*)d_in[5];
    const float* ln1b    = (const float*)d_in[6];
    const float* ln2w    = (const float*)d_in[7];
    const float* ln2b    = (const float*)d_in[8];
    const float* ln3w    = (const float*)d_in[9];
    const float* ln3b    = (const float*)d_in[10];
    float* out = (float*)d_out;

    static bool attr_done = false;
    if (!attr_done){
        cudaFuncSetAttribute(k1_conv1x1, cudaFuncAttributeMaxDynamicSharedMemorySize, 81920);
        cudaFuncSetAttribute(k4_proj,    cudaFuncAttributeMaxDynamicSharedMemorySize, 82688);
        attr_done = true;
    }

    k1_conv1x1<<<dim3(5, 256, 2), 256, 81920>>>(x, w_hidden);
    k3_fft<<<4864, 256>>>(w_dw, fparam);
    k4_proj<<<dim3(1024, 2), 256, 82688>>>(w_proj, ln1w, ln1b, ln2w, ln2b, ln3w, ln3b, out);
}